// round 5
// baseline (speedup 1.0000x reference)
#include <cuda_runtime.h>

// ScaledDotProductAttention: B=4, H=1, S=4096, D=16, fp32.
// out = [context (B*S*D) | attn (B*S*S)]
// scores = QK^T/4 + (w*link + b); masked(true) -> -1e9; softmax; context = attn @ V.
// Scores bounded (|s| << 88) -> softmax = exp(s)/sum(exp(s)), no max pass.
// TQ=4 -> 64KB smem -> 2 CTAs/SM (16 warps) for latency hiding.

#define BATCH 4
#define SEQ   4096
#define DIM   16
#define TQ    4            // q-rows per CTA
#define NT    256          // threads per CTA
#define NWARP (NT / 32)

#define SMEM_BYTES (TQ * SEQ * 4)   // 65536 B exp(score) buffer

__global__ __launch_bounds__(NT, 2)
void sdpa_fused_kernel(const float* __restrict__ Qp,
                       const float* __restrict__ Kp,
                       const float* __restrict__ Vp,
                       const int*   __restrict__ Mp,
                       const float* __restrict__ Lp,
                       const float* __restrict__ swp,
                       const float* __restrict__ sbp,
                       float* __restrict__ ctx,
                       float* __restrict__ attn)
{
    extern __shared__ float scr[];                 // TQ*SEQ exp(scores)
    __shared__ float qs[TQ * DIM];
    __shared__ float redw[TQ * NWARP];
    __shared__ float sinv[TQ];
    __shared__ float redc[NWARP * TQ * DIM];       // context partials (2 KB)

    const int tid = threadIdx.x;
    const int wp  = tid >> 5;
    const int ln  = tid & 31;
    const int b   = blockIdx.x / (SEQ / TQ);
    const int q0  = (blockIdx.x % (SEQ / TQ)) * TQ;

    const float w  = *swp;
    const float bb = *sbp;

    if (tid < TQ * DIM)
        qs[tid] = Qp[((size_t)b * SEQ + q0) * DIM + tid];
    __syncthreads();

    float qreg[TQ * DIM];
    #pragma unroll
    for (int i = 0; i < TQ * DIM; i++) qreg[i] = qs[i];

    const float4* K4 = (const float4*)(Kp + (size_t)b * SEQ * DIM);
    const float4* V4 = (const float4*)(Vp + (size_t)b * SEQ * DIM);
    const float*  Lb = Lp + (size_t)b * SEQ * SEQ;
    const int*    Mb = Mp + (size_t)b * SEQ * SEQ;
    float* Ab = attn + (size_t)b * SEQ * SEQ;

    // ============ Phase A: e = exp(score) -> smem; accumulate row sums ============
    float sloc[TQ];
    #pragma unroll
    for (int q = 0; q < TQ; q++) sloc[q] = 0.0f;

    #pragma unroll 2
    for (int k = tid; k < SEQ; k += NT) {
        float4 k0 = K4[4 * k + 0];
        float4 k1 = K4[4 * k + 1];
        float4 k2 = K4[4 * k + 2];
        float4 k3 = K4[4 * k + 3];
        float lk[TQ];
        int   mk[TQ];
        #pragma unroll
        for (int q = 0; q < TQ; q++) lk[q] = Lb[(size_t)(q0 + q) * SEQ + k];
        #pragma unroll
        for (int q = 0; q < TQ; q++) mk[q] = Mb[(size_t)(q0 + q) * SEQ + k];

        #pragma unroll
        for (int q = 0; q < TQ; q++) {
            const float* qq = &qreg[q * DIM];
            float dot;
            dot = qq[0]  * k0.x;            dot = fmaf(qq[1],  k0.y, dot);
            dot = fmaf(qq[2],  k0.z, dot);  dot = fmaf(qq[3],  k0.w, dot);
            dot = fmaf(qq[4],  k1.x, dot);  dot = fmaf(qq[5],  k1.y, dot);
            dot = fmaf(qq[6],  k1.z, dot);  dot = fmaf(qq[7],  k1.w, dot);
            dot = fmaf(qq[8],  k2.x, dot);  dot = fmaf(qq[9],  k2.y, dot);
            dot = fmaf(qq[10], k2.z, dot);  dot = fmaf(qq[11], k2.w, dot);
            dot = fmaf(qq[12], k3.x, dot);  dot = fmaf(qq[13], k3.y, dot);
            dot = fmaf(qq[14], k3.z, dot);  dot = fmaf(qq[15], k3.w, dot);
            float sc = fmaf(w, lk[q], bb);
            sc = fmaf(dot, 0.25f, sc);                 // 1/sqrt(16)
            sc = mk[q] ? -1e9f : sc;                   // expf(-1e9) == 0
            float e = __expf(sc);
            scr[q * SEQ + k] = e;
            sloc[q] += e;
        }
    }

    // ---- reduce row sums ----
    #pragma unroll
    for (int q = 0; q < TQ; q++) {
        #pragma unroll
        for (int o = 16; o > 0; o >>= 1)
            sloc[q] += __shfl_xor_sync(0xffffffffu, sloc[q], o);
    }
    if (ln == 0) {
        #pragma unroll
        for (int q = 0; q < TQ; q++) redw[q * NWARP + wp] = sloc[q];
    }
    __syncthreads();
    if (tid < TQ) {
        float s = 0.0f;
        #pragma unroll
        for (int t = 0; t < NWARP; t++) s += redw[tid * NWARP + t];
        sinv[tid] = 1.0f / s;
    }
    __syncthreads();

    // ============ Phase E: attn = e * inv; context accumulate ============
    float inv[TQ];
    #pragma unroll
    for (int q = 0; q < TQ; q++) inv[q] = sinv[q];

    float acc[TQ * DIM];
    #pragma unroll
    for (int i = 0; i < TQ * DIM; i++) acc[i] = 0.0f;

    #pragma unroll 2
    for (int k = tid; k < SEQ; k += NT) {
        float4 v0 = V4[4 * k + 0];
        float4 v1 = V4[4 * k + 1];
        float4 v2 = V4[4 * k + 2];
        float4 v3 = V4[4 * k + 3];
        #pragma unroll
        for (int q = 0; q < TQ; q++) {
            float a = scr[q * SEQ + k] * inv[q];
            Ab[(size_t)(q0 + q) * SEQ + k] = a;
            float* A = &acc[q * DIM];
            A[0]  = fmaf(a, v0.x, A[0]);  A[1]  = fmaf(a, v0.y, A[1]);
            A[2]  = fmaf(a, v0.z, A[2]);  A[3]  = fmaf(a, v0.w, A[3]);
            A[4]  = fmaf(a, v1.x, A[4]);  A[5]  = fmaf(a, v1.y, A[5]);
            A[6]  = fmaf(a, v1.z, A[6]);  A[7]  = fmaf(a, v1.w, A[7]);
            A[8]  = fmaf(a, v2.x, A[8]);  A[9]  = fmaf(a, v2.y, A[9]);
            A[10] = fmaf(a, v2.z, A[10]); A[11] = fmaf(a, v2.w, A[11]);
            A[12] = fmaf(a, v3.x, A[12]); A[13] = fmaf(a, v3.y, A[13]);
            A[14] = fmaf(a, v3.z, A[14]); A[15] = fmaf(a, v3.w, A[15]);
        }
    }

    // ---- multi-value warp butterfly: 64 sums -> lane ln owns {2ln, 2ln+1} ----
    #pragma unroll
    for (int o = 16, n = 32; o >= 1; o >>= 1, n >>= 1) {
        const bool hi = (ln & o) != 0;
        #pragma unroll
        for (int i = 0; i < n; i++) {
            float s    = hi ? acc[i] : acc[i + n];
            float r    = __shfl_xor_sync(0xffffffffu, s, o);
            float mine = hi ? acc[i + n] : acc[i];
            acc[i] = mine + r;
        }
    }
    *(float2*)&redc[wp * (TQ * DIM) + 2 * ln] = make_float2(acc[0], acc[1]);
    __syncthreads();

    if (tid < TQ * DIM) {
        float s = 0.0f;
        #pragma unroll
        for (int ww = 0; ww < NWARP; ww++)
            s += redc[ww * (TQ * DIM) + tid];
        const int q = tid >> 4, d = tid & 15;
        ctx[((size_t)b * SEQ + q0 + q) * DIM + d] = s;
    }
}

extern "C" void kernel_launch(void* const* d_in, const int* in_sizes, int n_in,
                              void* d_out, int out_size)
{
    const float* Q  = (const float*)d_in[0];
    const float* K  = (const float*)d_in[1];
    const float* V  = (const float*)d_in[2];
    const int*   M  = (const int*)d_in[3];
    const float* L  = (const float*)d_in[4];
    const float* sw = (const float*)d_in[5];
    const float* sb = (const float*)d_in[6];

    float* ctx  = (float*)d_out;                               // B*S*D
    float* attn = (float*)d_out + (size_t)BATCH * SEQ * DIM;   // B*S*S

    cudaFuncSetAttribute(sdpa_fused_kernel,
                         cudaFuncAttributeMaxDynamicSharedMemorySize, SMEM_BYTES);

    dim3 grid(BATCH * (SEQ / TQ));
    sdpa_fused_kernel<<<grid, NT, SMEM_BYTES>>>(Q, K, V, M, L, sw, sb, ctx, attn);
}

// round 6
// speedup vs baseline: 1.2163x; 1.2163x over previous
#include <cuda_runtime.h>

// ScaledDotProductAttention: B=4, H=1, S=4096, D=16, fp32.
// out = [context (B*S*D) | attn (B*S*S)]
// scores = QK^T/4 + (w*link + b); masked(true) -> -1e9; softmax; context = attn @ V.
// Softmax without max pass (scores bounded; expf(-1e9)==0).
// d-dimension packed into f32x2 -> FFMA2 halves FMA instruction count.

#define BATCH 4
#define SEQ   4096
#define DIM   16
#define TQ    8            // q-rows per CTA
#define NT    256          // threads per CTA
#define NWARP (NT / 32)

#define SMEM_BYTES (TQ * SEQ * 4)   // 131072 B exp(score) buffer

typedef unsigned long long u64;

__device__ __forceinline__ u64 pk2(float lo, float hi) {
    u64 r;
    asm("mov.b64 %0, {%1, %2};" : "=l"(r) : "f"(lo), "f"(hi));
    return r;
}
__device__ __forceinline__ void upk2(u64 v, float& lo, float& hi) {
    asm("mov.b64 {%0, %1}, %2;" : "=f"(lo), "=f"(hi) : "l"(v));
}
__device__ __forceinline__ u64 fma2(u64 a, u64 b, u64 c) {
    u64 d;
    asm("fma.rn.f32x2 %0, %1, %2, %3;" : "=l"(d) : "l"(a), "l"(b), "l"(c));
    return d;
}
__device__ __forceinline__ u64 mul2(u64 a, u64 b) {
    u64 d;
    asm("mul.rn.f32x2 %0, %1, %2;" : "=l"(d) : "l"(a), "l"(b));
    return d;
}

__global__ __launch_bounds__(NT, 1)
void sdpa_fused_kernel(const float* __restrict__ Qp,
                       const float* __restrict__ Kp,
                       const float* __restrict__ Vp,
                       const int*   __restrict__ Mp,
                       const float* __restrict__ Lp,
                       const float* __restrict__ swp,
                       const float* __restrict__ sbp,
                       float* __restrict__ ctx,
                       float* __restrict__ attn)
{
    extern __shared__ float scr[];                 // TQ*SEQ exp(scores)
    __shared__ float qs[TQ * DIM];
    __shared__ float redw[TQ * NWARP];
    __shared__ float sinv[TQ];
    __shared__ float redc[NWARP * 128];            // context partials (4 KB)

    const int tid = threadIdx.x;
    const int wp  = tid >> 5;
    const int ln  = tid & 31;
    const int b   = blockIdx.x / (SEQ / TQ);
    const int q0  = (blockIdx.x % (SEQ / TQ)) * TQ;

    const float w  = *swp;
    const float bb = *sbp;

    if (tid < TQ * DIM)
        qs[tid] = Qp[((size_t)b * SEQ + q0) * DIM + tid];
    __syncthreads();

    // Q tile packed as f32x2 pairs: q2[q*8 + i] = (Q[q][2i], Q[q][2i+1])
    u64 q2[TQ * 8];
    #pragma unroll
    for (int q = 0; q < TQ; q++)
        #pragma unroll
        for (int i = 0; i < 8; i++)
            q2[q * 8 + i] = pk2(qs[q * DIM + 2 * i], qs[q * DIM + 2 * i + 1]);

    const float4* K4 = (const float4*)(Kp + (size_t)b * SEQ * DIM);
    const float4* V4 = (const float4*)(Vp + (size_t)b * SEQ * DIM);
    const float*  Lb = Lp + (size_t)b * SEQ * SEQ;
    const int*    Mb = Mp + (size_t)b * SEQ * SEQ;
    float* Ab = attn + (size_t)b * SEQ * SEQ;

    // ============ Phase A: e = exp(score) -> smem; row sums ============
    float sloc[TQ];
    #pragma unroll
    for (int q = 0; q < TQ; q++) sloc[q] = 0.0f;

    #pragma unroll 2
    for (int k = tid; k < SEQ; k += NT) {
        float4 k0 = K4[4 * k + 0];
        float4 k1 = K4[4 * k + 1];
        float4 k2 = K4[4 * k + 2];
        float4 k3 = K4[4 * k + 3];
        u64 kk[8];
        kk[0] = pk2(k0.x, k0.y); kk[1] = pk2(k0.z, k0.w);
        kk[2] = pk2(k1.x, k1.y); kk[3] = pk2(k1.z, k1.w);
        kk[4] = pk2(k2.x, k2.y); kk[5] = pk2(k2.z, k2.w);
        kk[6] = pk2(k3.x, k3.y); kk[7] = pk2(k3.z, k3.w);

        float lk[TQ];
        int   mk[TQ];
        #pragma unroll
        for (int q = 0; q < TQ; q++) lk[q] = Lb[(size_t)(q0 + q) * SEQ + k];
        #pragma unroll
        for (int q = 0; q < TQ; q++) mk[q] = Mb[(size_t)(q0 + q) * SEQ + k];

        #pragma unroll
        for (int q = 0; q < TQ; q++) {
            const u64* qq = &q2[q * 8];
            u64 d2 = mul2(qq[0], kk[0]);
            d2 = fma2(qq[1], kk[1], d2);
            d2 = fma2(qq[2], kk[2], d2);
            d2 = fma2(qq[3], kk[3], d2);
            d2 = fma2(qq[4], kk[4], d2);
            d2 = fma2(qq[5], kk[5], d2);
            d2 = fma2(qq[6], kk[6], d2);
            d2 = fma2(qq[7], kk[7], d2);
            float dl, dh;
            upk2(d2, dl, dh);
            float dot = dl + dh;
            float sc = fmaf(w, lk[q], bb);
            sc = fmaf(dot, 0.25f, sc);                 // 1/sqrt(16)
            sc = mk[q] ? -1e9f : sc;                   // expf(-1e9) == 0
            float e = __expf(sc);
            scr[q * SEQ + k] = e;
            sloc[q] += e;
        }
    }

    // ---- reduce row sums ----
    #pragma unroll
    for (int q = 0; q < TQ; q++) {
        #pragma unroll
        for (int o = 16; o > 0; o >>= 1)
            sloc[q] += __shfl_xor_sync(0xffffffffu, sloc[q], o);
    }
    if (ln == 0) {
        #pragma unroll
        for (int q = 0; q < TQ; q++) redw[q * NWARP + wp] = sloc[q];
    }
    __syncthreads();
    if (tid < TQ) {
        float s = 0.0f;
        #pragma unroll
        for (int t = 0; t < NWARP; t++) s += redw[tid * NWARP + t];
        sinv[tid] = 1.0f / s;
    }
    __syncthreads();

    // ============ Phase E: attn = e * inv; context accumulate (packed) ============
    float inv[TQ];
    #pragma unroll
    for (int q = 0; q < TQ; q++) inv[q] = sinv[q];

    u64 acc2[TQ * 8];
    #pragma unroll
    for (int i = 0; i < TQ * 8; i++) acc2[i] = 0ull;

    #pragma unroll 2
    for (int k = tid; k < SEQ; k += NT) {
        float4 v0 = V4[4 * k + 0];
        float4 v1 = V4[4 * k + 1];
        float4 v2 = V4[4 * k + 2];
        float4 v3 = V4[4 * k + 3];
        u64 vv[8];
        vv[0] = pk2(v0.x, v0.y); vv[1] = pk2(v0.z, v0.w);
        vv[2] = pk2(v1.x, v1.y); vv[3] = pk2(v1.z, v1.w);
        vv[4] = pk2(v2.x, v2.y); vv[5] = pk2(v2.z, v2.w);
        vv[6] = pk2(v3.x, v3.y); vv[7] = pk2(v3.z, v3.w);

        #pragma unroll
        for (int q = 0; q < TQ; q++) {
            float a = scr[q * SEQ + k] * inv[q];
            Ab[(size_t)(q0 + q) * SEQ + k] = a;
            u64 aa = pk2(a, a);
            u64* A = &acc2[q * 8];
            A[0] = fma2(aa, vv[0], A[0]);
            A[1] = fma2(aa, vv[1], A[1]);
            A[2] = fma2(aa, vv[2], A[2]);
            A[3] = fma2(aa, vv[3], A[3]);
            A[4] = fma2(aa, vv[4], A[4]);
            A[5] = fma2(aa, vv[5], A[5]);
            A[6] = fma2(aa, vv[6], A[6]);
            A[7] = fma2(aa, vv[7], A[7]);
        }
    }

    // ---- unpack, then multi-value warp butterfly: lane ln owns {4ln..4ln+3} ----
    float acc[TQ * DIM];
    #pragma unroll
    for (int i = 0; i < TQ * 8; i++)
        upk2(acc2[i], acc[2 * i], acc[2 * i + 1]);

    #pragma unroll
    for (int o = 16, n = 64; o >= 1; o >>= 1, n >>= 1) {
        const bool hi = (ln & o) != 0;
        #pragma unroll
        for (int i = 0; i < n; i++) {
            float s    = hi ? acc[i] : acc[i + n];
            float r    = __shfl_xor_sync(0xffffffffu, s, o);
            float mine = hi ? acc[i + n] : acc[i];
            acc[i] = mine + r;
        }
    }
    *(float4*)&redc[wp * 128 + 4 * ln] = make_float4(acc[0], acc[1], acc[2], acc[3]);
    __syncthreads();

    if (tid < 128) {
        float s = 0.0f;
        #pragma unroll
        for (int ww = 0; ww < NWARP; ww++)
            s += redc[ww * 128 + tid];
        const int q = tid >> 4, d = tid & 15;
        ctx[((size_t)b * SEQ + q0 + q) * DIM + d] = s;
    }
}

extern "C" void kernel_launch(void* const* d_in, const int* in_sizes, int n_in,
                              void* d_out, int out_size)
{
    const float* Q  = (const float*)d_in[0];
    const float* K  = (const float*)d_in[1];
    const float* V  = (const float*)d_in[2];
    const int*   M  = (const int*)d_in[3];
    const float* L  = (const float*)d_in[4];
    const float* sw = (const float*)d_in[5];
    const float* sb = (const float*)d_in[6];

    float* ctx  = (float*)d_out;                               // B*S*D
    float* attn = (float*)d_out + (size_t)BATCH * SEQ * DIM;   // B*S*S

    cudaFuncSetAttribute(sdpa_fused_kernel,
                         cudaFuncAttributeMaxDynamicSharedMemorySize, SMEM_BYTES);

    dim3 grid(BATCH * (SEQ / TQ));
    sdpa_fused_kernel<<<grid, NT, SMEM_BYTES>>>(Q, K, V, M, L, sw, sb, ctx, attn);
}